// round 5
// baseline (speedup 1.0000x reference)
#include <cuda_runtime.h>
#include <cstdint>

// DerivativeNet forward, direction='x'.
//   out = eroded * central_diff + edge1 * fwd_diff + edge2 * bwd_diff
// where eroded = 1x3 box(mask)==3, edge1 = (cumsum(mask)==1),
// edge2 = (cumsum==rowmax)&mask.
//
// edge1 is exactly the half-open index range [first_true, second_true);
// edge2 is exactly {last_true}. No scan needed — first/second/last True
// indices per row, found with REDUX warp reductions + 8 shared atomics.
//
// Layout: u [B,C,H,W], mask [B,1,H,W], W=1024, fp32, C=2.
// One 256-thread CTA per (b,h) row; each thread owns 4 contiguous
// elements (one float4 per array). mask + both u channels are loaded
// back-to-back up front (MLP=3) so DRAM latency overlaps the mask
// reduction. Mask row read once, reused for both channels -> HBM
// traffic at the ~335 MB floor.

#ifndef INT_MAX_C
#define INT_MAX_C 0x7fffffff
#endif

template <int C, int LOG2H>
__global__ __launch_bounds__(256) void deriv_x_kernel(
    const float* __restrict__ u,
    const float* __restrict__ mask,
    float* __restrict__ out)
{
    constexpr int W = 1024;
    constexpr int T = 256;
    constexpr int H = 1 << LOG2H;
    const float inv2h = 50.0f;   // 1/(2*0.01)
    const float invh  = 100.0f;  // 1/0.01

    __shared__ float s_mL[T], s_mR[T];
    __shared__ float s_uL[C][T], s_uR[C][T];
    __shared__ int   s_first, s_second, s_last;

    const int tid = threadIdx.x;
    const int row = blockIdx.x;        // 0 .. B*H-1
    const int b   = row >> LOG2H;
    const int hh  = row & (H - 1);

    // ---- front-batched loads: mask + all C channels (MLP = C+1) ----
    const float4 m = reinterpret_cast<const float4*>(
        mask + (size_t)row * W)[tid];

    float4 uv[C];
    size_t uoff[C];
    uoff[0] = (((size_t)b * C) * (size_t)H + hh) * W;
    #pragma unroll
    for (int c = 1; c < C; c++) uoff[c] = uoff[c - 1] + (size_t)H * W;
    #pragma unroll
    for (int c = 0; c < C; c++)
        uv[c] = reinterpret_cast<const float4*>(u + uoff[c])[tid];

    if (tid == 0) { s_first = INT_MAX_C; s_second = INT_MAX_C; s_last = -1; }
    s_mL[tid] = m.x;
    s_mR[tid] = m.w;
    // publish u halos early; consumed only after the 3rd barrier
    #pragma unroll
    for (int c = 0; c < C; c++) {
        s_uL[c][tid] = uv[c].x;
        s_uR[c][tid] = uv[c].w;
    }

    const float mv[4] = {m.x, m.y, m.z, m.w};
    const int base = tid * 4;

    // per-thread first/second/last True indices
    int lf = INT_MAX_C, ls = INT_MAX_C, ll = -1;
    #pragma unroll
    for (int i = 0; i < 4; i++) {
        if (mv[i] != 0.0f) {
            if (lf == INT_MAX_C)      lf = base + i;
            else if (ls == INT_MAX_C) ls = base + i;
            ll = base + i;
        }
    }
    __syncthreads();   // barrier 1: s_first/s_second/s_last init visible

    // warp-level REDUX, then one shared atomic per warp
    {
        const int wf = __reduce_min_sync(0xffffffffu, lf);
        const int wl = __reduce_max_sync(0xffffffffu, ll);
        if ((tid & 31) == 0) {
            if (wf != INT_MAX_C) atomicMin(&s_first, wf);
            if (wl >= 0)         atomicMax(&s_last,  wl);
        }
    }
    __syncthreads();   // barrier 2: s_first final

    const int first = s_first;
    // global second-smallest True index: per-thread candidate is the
    // smallest in-thread True index strictly greater than `first`
    {
        int cand = INT_MAX_C;
        if (lf != INT_MAX_C) cand = (lf > first) ? lf : ls;
        const int wc = __reduce_min_sync(0xffffffffu, cand);
        if ((tid & 31) == 0 && wc != INT_MAX_C) atomicMin(&s_second, wc);
    }
    __syncthreads();   // barrier 3: s_second final; halos readable

    const int second = s_second;  // INT_MAX if <2 True -> edge1 runs to row end
    const int last   = s_last;    // -1 if no True

    // eroded mask for this thread's 4 elements (with zero pad)
    float er[4];
    #pragma unroll
    for (int i = 0; i < 4; i++) {
        const float ml = (i > 0)     ? mv[i - 1] : (tid > 0     ? s_mR[tid - 1] : 0.0f);
        const float mr = (i < 3)     ? mv[i + 1] : (tid < T - 1 ? s_mL[tid + 1] : 0.0f);
        er[i] = (ml + mv[i] + mr == 3.0f) ? 1.0f : 0.0f;
    }

    #pragma unroll
    for (int c = 0; c < C; c++) {
        const float uvv[4] = {uv[c].x, uv[c].y, uv[c].z, uv[c].w};
        float o[4];
        #pragma unroll
        for (int i = 0; i < 4; i++) {
            const int j = base + i;
            const float uc = uvv[i];
            const float ul = (i > 0)     ? uvv[i - 1] : (tid > 0     ? s_uR[c][tid - 1] : 0.0f);
            const float ur = (i < 3)     ? uvv[i + 1] : (tid < T - 1 ? s_uL[c][tid + 1] : 0.0f);

            const float internal_d = (ur - ul) * inv2h;  // central diff
            const float left_d     = (ur - uc) * invh;   // forward diff
            const float right_d    = (uc - ul) * invh;   // backward diff

            float res = er[i] * internal_d;
            if (j >= first && j < second) res += left_d;   // edge1 range
            if (j == last)                res += right_d;  // edge2 point
            o[i] = res;
        }
        reinterpret_cast<float4*>(out + uoff[c])[tid] =
            make_float4(o[0], o[1], o[2], o[3]);
    }
}

// generic fallback (runtime C and H, same math)
__global__ __launch_bounds__(256) void deriv_x_kernel_dyn(
    const float* __restrict__ u,
    const float* __restrict__ mask,
    float* __restrict__ out,
    int C, int H)
{
    constexpr int W = 1024;
    constexpr int T = 256;
    const float inv2h = 50.0f;
    const float invh  = 100.0f;

    __shared__ float s_mL[T], s_mR[T];
    __shared__ float s_uL[T], s_uR[T];
    __shared__ int   s_first, s_second, s_last;

    const int tid = threadIdx.x;
    const int row = blockIdx.x;
    const int b   = row / H;
    const int hh  = row - b * H;

    const float4 m = reinterpret_cast<const float4*>(mask + (size_t)row * W)[tid];

    if (tid == 0) { s_first = INT_MAX_C; s_second = INT_MAX_C; s_last = -1; }
    s_mL[tid] = m.x;
    s_mR[tid] = m.w;

    const float mv[4] = {m.x, m.y, m.z, m.w};
    const int base = tid * 4;

    int lf = INT_MAX_C, ls = INT_MAX_C, ll = -1;
    #pragma unroll
    for (int i = 0; i < 4; i++) {
        if (mv[i] != 0.0f) {
            if (lf == INT_MAX_C)      lf = base + i;
            else if (ls == INT_MAX_C) ls = base + i;
            ll = base + i;
        }
    }
    __syncthreads();
    {
        const int wf = __reduce_min_sync(0xffffffffu, lf);
        const int wl = __reduce_max_sync(0xffffffffu, ll);
        if ((tid & 31) == 0) {
            if (wf != INT_MAX_C) atomicMin(&s_first, wf);
            if (wl >= 0)         atomicMax(&s_last,  wl);
        }
    }
    __syncthreads();

    const int first = s_first;
    {
        int cand = INT_MAX_C;
        if (lf != INT_MAX_C) cand = (lf > first) ? lf : ls;
        const int wc = __reduce_min_sync(0xffffffffu, cand);
        if ((tid & 31) == 0 && wc != INT_MAX_C) atomicMin(&s_second, wc);
    }
    __syncthreads();

    const int second = s_second;
    const int last   = s_last;

    float er[4];
    #pragma unroll
    for (int i = 0; i < 4; i++) {
        const float ml = (i > 0)     ? mv[i - 1] : (tid > 0     ? s_mR[tid - 1] : 0.0f);
        const float mr = (i < 3)     ? mv[i + 1] : (tid < T - 1 ? s_mL[tid + 1] : 0.0f);
        er[i] = (ml + mv[i] + mr == 3.0f) ? 1.0f : 0.0f;
    }

    for (int c = 0; c < C; c++) {
        const size_t uoff = (((size_t)b * C + c) * (size_t)H + hh) * W;
        const float4 uvc = reinterpret_cast<const float4*>(u + uoff)[tid];

        s_uL[tid] = uvc.x;
        s_uR[tid] = uvc.w;
        __syncthreads();

        const float uvv[4] = {uvc.x, uvc.y, uvc.z, uvc.w};
        float o[4];
        #pragma unroll
        for (int i = 0; i < 4; i++) {
            const int j = base + i;
            const float uc = uvv[i];
            const float ul = (i > 0)     ? uvv[i - 1] : (tid > 0     ? s_uR[tid - 1] : 0.0f);
            const float ur = (i < 3)     ? uvv[i + 1] : (tid < T - 1 ? s_uL[tid + 1] : 0.0f);

            const float internal_d = (ur - ul) * inv2h;
            const float left_d     = (ur - uc) * invh;
            const float right_d    = (uc - ul) * invh;

            float res = er[i] * internal_d;
            if (j >= first && j < second) res += left_d;
            if (j == last)                res += right_d;
            o[i] = res;
        }
        reinterpret_cast<float4*>(out + uoff)[tid] =
            make_float4(o[0], o[1], o[2], o[3]);
        __syncthreads();
    }
}

extern "C" void kernel_launch(void* const* d_in, const int* in_sizes, int n_in,
                              void* d_out, int out_size)
{
    const float* u    = (const float*)d_in[0];
    const float* mask = (const float*)d_in[1];
    float*       out  = (float*)d_out;

    const int W = 1024;
    const int rows = in_sizes[1] / W;             // B * H  (mask has C=1)
    const int C    = in_sizes[0] / in_sizes[1];   // = 2

    // H is 1024 in this problem; rows = B*H with B=16.
    if (C == 2 && (rows & 1023) == 0) {
        deriv_x_kernel<2, 10><<<rows, 256>>>(u, mask, out);
    } else {
        deriv_x_kernel_dyn<<<rows, 256>>>(u, mask, out, C, 1024);
    }
}

// round 6
// speedup vs baseline: 1.0012x; 1.0012x over previous
#include <cuda_runtime.h>
#include <cstdint>

// DerivativeNet forward, direction='x'.
//   out = eroded * central_diff + edge1 * fwd_diff + edge2 * bwd_diff
// eroded = 1x3 box(mask)==3; edge1 = (cumsum==1) == index range
// [first_true, second_true); edge2 = (cumsum==rowmax)&mask == {last_true}.
//
// R5 design: 2 rows per CTA, 6 front-batched LDG.128 (MLP=6), ONE
// barrier total. Per-warp (first, second, last) triples go to shared;
// after the single barrier every thread scans the 8 warp entries:
//   global_first  = min_i wf[i]
//   global_second = min_i (wf[i]==first ? ws[i] : wf[i])   (indices distinct)
//   global_last   = max_i wl[i]
// Mask row read once, reused for both channels -> ~335 MB HBM floor.
// Measured R4 baseline: 45.7us kernel, DRAM 78.2%.

#ifndef INT_MAX_C
#define INT_MAX_C 0x7fffffff
#endif

template <int C, int R, int LOG2H>
__global__ __launch_bounds__(256, 4) void deriv_x_kernel(
    const float* __restrict__ u,
    const float* __restrict__ mask,
    float* __restrict__ out)
{
    constexpr int W = 1024;
    constexpr int T = 256;
    constexpr int NW = T / 32;           // 8 warps
    constexpr int H = 1 << LOG2H;
    const float inv2h = 50.0f;           // 1/(2*0.01)
    const float invh  = 100.0f;          // 1/0.01

    __shared__ float s_mL[R][T], s_mR[R][T];
    __shared__ float s_uL[R][C][T], s_uR[R][C][T];
    __shared__ int   s_wf[R][NW], s_ws[R][NW], s_wl[R][NW];

    const int tid  = threadIdx.x;
    const int wid  = tid >> 5;
    const int lane = tid & 31;
    const int row0 = blockIdx.x * R;
    const int base = tid * 4;

    // ---- front-batched loads: R mask rows + R*C u rows (MLP = R*(C+1)) ----
    float4 m[R];
    float4 uv[R][C];
    size_t uoff[R][C];
    #pragma unroll
    for (int r = 0; r < R; r++) {
        const int row = row0 + r;
        const int b   = row >> LOG2H;
        const int hh  = row & (H - 1);
        m[r] = reinterpret_cast<const float4*>(mask + (size_t)row * W)[tid];
        uoff[r][0] = (((size_t)b * C) * (size_t)H + hh) * W;
        #pragma unroll
        for (int c = 1; c < C; c++) uoff[r][c] = uoff[r][c - 1] + (size_t)H * W;
        #pragma unroll
        for (int c = 0; c < C; c++)
            uv[r][c] = reinterpret_cast<const float4*>(u + uoff[r][c])[tid];
    }

    // publish halos (consumed after the single barrier)
    #pragma unroll
    for (int r = 0; r < R; r++) {
        s_mL[r][tid] = m[r].x;
        s_mR[r][tid] = m[r].w;
        #pragma unroll
        for (int c = 0; c < C; c++) {
            s_uL[r][c][tid] = uv[r][c].x;
            s_uR[r][c][tid] = uv[r][c].w;
        }
    }

    // per-thread first/second/last True indices, then warp triples
    int lf[R], ls[R], ll[R];
    #pragma unroll
    for (int r = 0; r < R; r++) {
        const float mvr[4] = {m[r].x, m[r].y, m[r].z, m[r].w};
        int f = INT_MAX_C, s = INT_MAX_C, l = -1;
        #pragma unroll
        for (int i = 0; i < 4; i++) {
            if (mvr[i] != 0.0f) {
                if (f == INT_MAX_C)      f = base + i;
                else if (s == INT_MAX_C) s = base + i;
                l = base + i;
            }
        }
        lf[r] = f; ls[r] = s; ll[r] = l;

        const int wf = __reduce_min_sync(0xffffffffu, f);
        const int wl = __reduce_max_sync(0xffffffffu, l);
        const int cand2 = (f == wf) ? s : f;        // distinct indices -> unique argmin
        const int ws = __reduce_min_sync(0xffffffffu, cand2);
        if (lane == 0) {
            s_wf[r][wid] = wf;
            s_ws[r][wid] = ws;
            s_wl[r][wid] = wl;
        }
    }

    __syncthreads();   // the ONLY barrier: warp triples + all halos visible

    #pragma unroll
    for (int r = 0; r < R; r++) {
        // scan the 8 warp entries
        int first = INT_MAX_C, last = -1;
        #pragma unroll
        for (int i = 0; i < NW; i++) {
            first = min(first, s_wf[r][i]);
            last  = max(last,  s_wl[r][i]);
        }
        int second = INT_MAX_C;
        #pragma unroll
        for (int i = 0; i < NW; i++) {
            const int v = (s_wf[r][i] == first) ? s_ws[r][i] : s_wf[r][i];
            second = min(second, v);
        }

        // eroded mask for this thread's 4 elements (zero pad at row ends)
        const float mvr[4] = {m[r].x, m[r].y, m[r].z, m[r].w};
        float er[4];
        #pragma unroll
        for (int i = 0; i < 4; i++) {
            const float ml = (i > 0) ? mvr[i - 1]
                             : (tid > 0     ? s_mR[r][tid - 1] : 0.0f);
            const float mr = (i < 3) ? mvr[i + 1]
                             : (tid < T - 1 ? s_mL[r][tid + 1] : 0.0f);
            er[i] = (ml + mvr[i] + mr == 3.0f) ? 1.0f : 0.0f;
        }

        #pragma unroll
        for (int c = 0; c < C; c++) {
            const float uvv[4] = {uv[r][c].x, uv[r][c].y, uv[r][c].z, uv[r][c].w};
            float o[4];
            #pragma unroll
            for (int i = 0; i < 4; i++) {
                const int j = base + i;
                const float uc = uvv[i];
                const float ul = (i > 0) ? uvv[i - 1]
                                 : (tid > 0     ? s_uR[r][c][tid - 1] : 0.0f);
                const float ur = (i < 3) ? uvv[i + 1]
                                 : (tid < T - 1 ? s_uL[r][c][tid + 1] : 0.0f);

                const float internal_d = (ur - ul) * inv2h;  // central diff
                const float left_d     = (ur - uc) * invh;   // forward diff
                const float right_d    = (uc - ul) * invh;   // backward diff

                float res = er[i] * internal_d;
                if (j >= first && j < second) res += left_d;   // edge1 range
                if (j == last)                res += right_d;  // edge2 point
                o[i] = res;
            }
            reinterpret_cast<float4*>(out + uoff[r][c])[tid] =
                make_float4(o[0], o[1], o[2], o[3]);
        }
    }
}

// generic fallback (runtime C and H, same math, 1 row per CTA)
__global__ __launch_bounds__(256) void deriv_x_kernel_dyn(
    const float* __restrict__ u,
    const float* __restrict__ mask,
    float* __restrict__ out,
    int C, int H)
{
    constexpr int W = 1024;
    constexpr int T = 256;
    const float inv2h = 50.0f;
    const float invh  = 100.0f;

    __shared__ float s_mL[T], s_mR[T];
    __shared__ float s_uL[T], s_uR[T];
    __shared__ int   s_first, s_second, s_last;

    const int tid = threadIdx.x;
    const int row = blockIdx.x;
    const int b   = row / H;
    const int hh  = row - b * H;

    const float4 m = reinterpret_cast<const float4*>(mask + (size_t)row * W)[tid];

    if (tid == 0) { s_first = INT_MAX_C; s_second = INT_MAX_C; s_last = -1; }
    s_mL[tid] = m.x;
    s_mR[tid] = m.w;

    const float mv[4] = {m.x, m.y, m.z, m.w};
    const int base = tid * 4;

    int lf = INT_MAX_C, ls = INT_MAX_C, ll = -1;
    #pragma unroll
    for (int i = 0; i < 4; i++) {
        if (mv[i] != 0.0f) {
            if (lf == INT_MAX_C)      lf = base + i;
            else if (ls == INT_MAX_C) ls = base + i;
            ll = base + i;
        }
    }
    __syncthreads();
    {
        const int wf = __reduce_min_sync(0xffffffffu, lf);
        const int wl = __reduce_max_sync(0xffffffffu, ll);
        if ((tid & 31) == 0) {
            if (wf != INT_MAX_C) atomicMin(&s_first, wf);
            if (wl >= 0)         atomicMax(&s_last,  wl);
        }
    }
    __syncthreads();

    const int first = s_first;
    {
        int cand = INT_MAX_C;
        if (lf != INT_MAX_C) cand = (lf > first) ? lf : ls;
        const int wc = __reduce_min_sync(0xffffffffu, cand);
        if ((tid & 31) == 0 && wc != INT_MAX_C) atomicMin(&s_second, wc);
    }
    __syncthreads();

    const int second = s_second;
    const int last   = s_last;

    float er[4];
    #pragma unroll
    for (int i = 0; i < 4; i++) {
        const float ml = (i > 0)     ? mv[i - 1] : (tid > 0     ? s_mR[tid - 1] : 0.0f);
        const float mr = (i < 3)     ? mv[i + 1] : (tid < T - 1 ? s_mL[tid + 1] : 0.0f);
        er[i] = (ml + mv[i] + mr == 3.0f) ? 1.0f : 0.0f;
    }

    for (int c = 0; c < C; c++) {
        const size_t uoff = (((size_t)b * C + c) * (size_t)H + hh) * W;
        const float4 uvc = reinterpret_cast<const float4*>(u + uoff)[tid];

        s_uL[tid] = uvc.x;
        s_uR[tid] = uvc.w;
        __syncthreads();

        const float uvv[4] = {uvc.x, uvc.y, uvc.z, uvc.w};
        float o[4];
        #pragma unroll
        for (int i = 0; i < 4; i++) {
            const int j = base + i;
            const float uc = uvv[i];
            const float ul = (i > 0)     ? uvv[i - 1] : (tid > 0     ? s_uR[tid - 1] : 0.0f);
            const float ur = (i < 3)     ? uvv[i + 1] : (tid < T - 1 ? s_uL[tid + 1] : 0.0f);

            const float internal_d = (ur - ul) * inv2h;
            const float left_d     = (ur - uc) * invh;
            const float right_d    = (uc - ul) * invh;

            float res = er[i] * internal_d;
            if (j >= first && j < second) res += left_d;
            if (j == last)                res += right_d;
            o[i] = res;
        }
        reinterpret_cast<float4*>(out + uoff)[tid] =
            make_float4(o[0], o[1], o[2], o[3]);
        __syncthreads();
    }
}

extern "C" void kernel_launch(void* const* d_in, const int* in_sizes, int n_in,
                              void* d_out, int out_size)
{
    const float* u    = (const float*)d_in[0];
    const float* mask = (const float*)d_in[1];
    float*       out  = (float*)d_out;

    const int W = 1024;
    const int rows = in_sizes[1] / W;             // B * H  (mask has C=1)
    const int C    = in_sizes[0] / in_sizes[1];   // = 2

    // H=1024 in this problem; rows = B*H, divisible by 2.
    if (C == 2 && (rows & 1023) == 0) {
        deriv_x_kernel<2, 2, 10><<<rows / 2, 256>>>(u, mask, out);
    } else {
        deriv_x_kernel_dyn<<<rows, 256>>>(u, mask, out, C, 1024);
    }
}